// round 10
// baseline (speedup 1.0000x reference)
#include <cuda_runtime.h>
#include <cuda_bf16.h>
#include <mma.h>
#include <math.h>

using namespace nvcuda;

#define BATCH 4096
#define NTAB  26
#define VOC   100000
#define EDIM  64
#define NPAIR 351
#define RDIM  416          // 64 + 351 padded (col 415 zeroed)

typedef __nv_bfloat16 bf16;
typedef long long ll;

// ---------------- scratch ----------------
__device__ bf16  g_bw1p[256 * 512];
__device__ bf16  g_bw2p[64 * 256];
__device__ bf16  g_tw0p[512 * RDIM];
__device__ bf16  g_tw1p[256 * 512];
__device__ bf16  g_h0  [BATCH * 512];
__device__ bf16  g_h1  [BATCH * 256];
__device__ bf16  g_R   [BATCH * RDIM];
__device__ bf16  g_z0  [BATCH * 512];
__device__ bf16  g_z1  [BATCH * 256];
__device__ float g_ly  [BATCH * NTAB * EDIM];

// ---------------- helpers ----------------
__device__ __forceinline__ unsigned su(const void* p) {
    return (unsigned)__cvta_generic_to_shared(p);
}
__device__ __forceinline__ void cpa16(unsigned d, const void* s) {
    asm volatile("cp.async.cg.shared.global [%0], [%1], 16;\n" :: "r"(d), "l"(s));
}

// ---------------- pack: fp32 -> bf16, K padded (weights for L2/L3/L4/L5) ----------
__global__ void __launch_bounds__(256)
pack_all(const float* bw1, const float* bw2, const float* tw0, const float* tw1)
{
    ll gid = (ll)blockIdx.x * 256 + threadIdx.x;
    const float* src; bf16* dst; int K, Kp; ll e;
    if (gid < 131072)       { src = bw1; dst = g_bw1p; K = 512; Kp = 512;  e = gid; }
    else if (gid < 147456)  { src = bw2; dst = g_bw2p; K = 256; Kp = 256;  e = gid - 131072; }
    else if (gid < 360448)  { src = tw0; dst = g_tw0p; K = 415; Kp = RDIM; e = gid - 147456; }
    else if (gid < 491520)  { src = tw1; dst = g_tw1p; K = 512; Kp = 512;  e = gid - 360448; }
    else return;
    int n = (int)(e / Kp), k = (int)(e % Kp);
    float v = (k < K) ? src[(ll)n * K + k] : 0.f;
    dst[e] = __float2bfloat16_rn(v);
}

// ---------------- L1 FFMA: h0 = relu(x[4096,13] @ bw0[512,13]^T + b), fp32 in ----
// Block = 32 rows; thread owns 2 columns (26 W regs); grid 128.
__global__ void __launch_bounds__(256)
mlp_l1(const float* __restrict__ x, const float* __restrict__ w,
       const float* __restrict__ bias, bf16* __restrict__ h0)
{
    __shared__ float xs[32][13];
    const int tid = threadIdx.x;
    const int r0  = blockIdx.x * 32;
    const int c0  = tid * 2;

    float wr[2][13];
#pragma unroll
    for (int j = 0; j < 2; j++)
#pragma unroll
        for (int k = 0; k < 13; k++) wr[j][k] = w[(c0 + j) * 13 + k];
    const float b0 = bias[c0], b1 = bias[c0 + 1];

    for (int i = tid; i < 32 * 13; i += 256)
        xs[i / 13][i % 13] = x[(ll)(r0 + i / 13) * 13 + i % 13];
    __syncthreads();

#pragma unroll 4
    for (int r = 0; r < 32; r++) {
        float xv[13];
#pragma unroll
        for (int k = 0; k < 13; k++) xv[k] = xs[r][k];
        float a0 = b0, a1 = b1;
#pragma unroll
        for (int k = 0; k < 13; k++) { a0 += xv[k] * wr[0][k]; a1 += xv[k] * wr[1][k]; }
        a0 = fmaxf(a0, 0.f); a1 = fmaxf(a1, 0.f);
        __nv_bfloat162 p = __floats2bfloat162_rn(a0, a1);
        *(__nv_bfloat162*)(h0 + (ll)(r0 + r) * 512 + c0) = p;
    }
}

// ---------------- L3 FFMA: R[:,0:64] = relu(h1[4096,256] @ bw2[64,256]^T + b) ----
// Block = 16 rows x 64 cols, grid 256. Smem bf16x2 words, stride 129 (odd) for
// conflict-free W reads; h1 reads are warp-broadcast.
__global__ void __launch_bounds__(256)
mlp_l3(const bf16* __restrict__ h1, const bf16* __restrict__ w,
       const float* __restrict__ bias, bf16* __restrict__ R)
{
    __shared__ unsigned Ws32[64 * 129];   // 33.0 KB
    __shared__ unsigned Hs32[16 * 129];   //  8.3 KB
    const int tid = threadIdx.x;
    const int r0  = blockIdx.x * 16;

    // load W: i -> (k2 = i&127, r = i>>7); gmem coalesced, smem banks k2-distinct
    for (int i = tid; i < 64 * 128; i += 256) {
        int k2 = i & 127, r = i >> 7;
        Ws32[r * 129 + k2] = *(const unsigned*)(w + r * 256 + 2 * k2);
    }
    for (int i = tid; i < 16 * 128; i += 256) {
        int k2 = i & 127, r = i >> 7;
        Hs32[r * 129 + k2] = *(const unsigned*)(h1 + (ll)(r0 + r) * 256 + 2 * k2);
    }
    __syncthreads();

    const int c  = tid & 63;
    const int rg = (tid >> 6) * 4;        // 4 row-groups of 4 rows
    float acc[4] = {0.f, 0.f, 0.f, 0.f};

    for (int kp = 0; kp < 128; kp++) {
        float2 wv = __bfloat1622float2(*(const __nv_bfloat162*)&Ws32[c * 129 + kp]);
#pragma unroll
        for (int j = 0; j < 4; j++) {
            float2 hv = __bfloat1622float2(*(const __nv_bfloat162*)&Hs32[(rg + j) * 129 + kp]);
            acc[j] += hv.x * wv.x + hv.y * wv.y;
        }
    }

    const float bv = bias[c];
#pragma unroll
    for (int j = 0; j < 4; j++) {
        float v = fmaxf(acc[j] + bv, 0.f);
        R[(ll)(r0 + rg + j) * RDIM + c] = __float2bfloat16_rn(v);
    }
}

// ---------------- pipelined bf16 GEMM (R4 config): BM=BN=64, BK=32, 128 thr ----
template <int ACT>
__global__ void __launch_bounds__(128, 6)
gemm_bf16(const bf16* __restrict__ A, const bf16* __restrict__ W,
          const float* __restrict__ bias, bf16* __restrict__ C, int Kp, int ldc)
{
    constexpr int BM = 64, BN = 64, BK = 32, LDT = 48, LDCs = 36;
    __shared__ __align__(16) bf16 sm[2][(BM + BN) * LDT];   // 24.6 KB

    const int bm   = blockIdx.y * BM;
    const int bn   = blockIdx.x * BN;
    const int tid  = threadIdx.x;
    const int wid  = tid >> 5;
    const int lane = tid & 31;
    const int warp_m = wid & 1;
    const int warp_n = wid >> 1;
    const int nk = Kp / BK;
    const int r0 = tid >> 2, c0 = (tid & 3) * 8;

    wmma::fragment<wmma::accumulator, 16, 16, 16, float> acc[2][2];
#pragma unroll
    for (int i = 0; i < 2; i++)
#pragma unroll
        for (int j = 0; j < 2; j++) wmma::fill_fragment(acc[i][j], 0.f);

    auto load_stage = [&](int st, int k0) {
        bf16* As = sm[st];
        bf16* Ws = As + BM * LDT;
        cpa16(su(As + r0 * LDT + c0),        A + (ll)(bm + r0) * Kp + k0 + c0);
        cpa16(su(As + (r0 + 32) * LDT + c0), A + (ll)(bm + r0 + 32) * Kp + k0 + c0);
        cpa16(su(Ws + r0 * LDT + c0),        W + (ll)(bn + r0) * Kp + k0 + c0);
        cpa16(su(Ws + (r0 + 32) * LDT + c0), W + (ll)(bn + r0 + 32) * Kp + k0 + c0);
        asm volatile("cp.async.commit_group;\n");
    };

    load_stage(0, 0);

    for (int it = 0; it < nk; it++) {
        if (it + 1 < nk) {
            load_stage((it + 1) & 1, (it + 1) * BK);
            asm volatile("cp.async.wait_group 1;\n");
        } else {
            asm volatile("cp.async.wait_group 0;\n");
        }
        __syncthreads();

        const bf16* As = sm[it & 1];
        const bf16* Ws = As + BM * LDT;
#pragma unroll
        for (int kk = 0; kk < BK; kk += 16) {
            wmma::fragment<wmma::matrix_a, 16, 16, 16, bf16, wmma::row_major> af[2];
            wmma::fragment<wmma::matrix_b, 16, 16, 16, bf16, wmma::col_major> bfg[2];
#pragma unroll
            for (int i = 0; i < 2; i++)
                wmma::load_matrix_sync(af[i], As + (warp_m * 32 + i * 16) * LDT + kk, LDT);
#pragma unroll
            for (int j = 0; j < 2; j++)
                wmma::load_matrix_sync(bfg[j], Ws + (warp_n * 32 + j * 16) * LDT + kk, LDT);
#pragma unroll
            for (int i = 0; i < 2; i++)
#pragma unroll
                for (int j = 0; j < 2; j++)
                    wmma::mma_sync(acc[i][j], af[i], bfg[j], acc[i][j]);
        }
        __syncthreads();
    }

    float* Cw = (float*)sm + wid * 32 * LDCs;
#pragma unroll
    for (int i = 0; i < 2; i++)
#pragma unroll
        for (int j = 0; j < 2; j++)
            wmma::store_matrix_sync(Cw + (i * 16) * LDCs + j * 16, acc[i][j], LDCs,
                                    wmma::mem_row_major);
    __syncwarp();

    const int n = bn + warp_n * 32 + lane;
    const float bv = bias[n];
#pragma unroll
    for (int r = 0; r < 32; r++) {
        int m = bm + warp_m * 32 + r;
        float v = Cw[r * LDCs + lane] + bv;
        if (ACT == 1) v = fmaxf(v, 0.f);
        C[(ll)m * ldc + n] = __float2bfloat16_rn(v);
    }
}

// ---------------- embedding gather-sum ----------------
__global__ void __launch_bounds__(256)
gather_kernel(const void* __restrict__ lsi, const float* __restrict__ emb,
              float* __restrict__ ly)
{
    const ll gid = (ll)blockIdx.x * 256 + threadIdx.x;
    if (gid >= (ll)BATCH * NTAB * 16) return;
    const int pair = (int)(gid >> 4);
    const int q4   = (int)(gid & 15);
    const int b = pair / NTAB;
    const int t = pair % NTAB;

    const unsigned long long* q = (const unsigned long long*)lsi;
    const bool is64 = (q[0] < (unsigned long long)VOC) && (q[1] < (unsigned long long)VOC) &&
                      (q[2] < (unsigned long long)VOC) && (q[3] < (unsigned long long)VOC);

    const ll base = ((ll)t * BATCH + b) * 4;
    float4 s = make_float4(0.f, 0.f, 0.f, 0.f);
#pragma unroll
    for (int l = 0; l < 4; l++) {
        int idx = is64 ? (int)((const ll*)lsi)[base + l]
                       : ((const int*)lsi)[base + l];
        float4 v = __ldg((const float4*)(emb + ((ll)t * VOC + idx) * EDIM + q4 * 4));
        s.x += v.x; s.y += v.y; s.z += v.z; s.w += v.w;
    }
    *(float4*)(ly + (ll)pair * EDIM + q4 * 4) = s;
}

// ---------------- interaction ----------------
__global__ void __launch_bounds__(128)
interact_kernel(const bf16* __restrict__ R_in, const float* __restrict__ ly,
                bf16* __restrict__ R)
{
    __shared__ float Ts[27][68];
    const int b   = blockIdx.x;
    const int tid = threadIdx.x;

    if (tid < 64) Ts[0][tid] = __bfloat162float(R_in[(ll)b * RDIM + tid]);
    const float* lyb = ly + (ll)b * NTAB * EDIM;
#pragma unroll
    for (int i = tid; i < NTAB * EDIM; i += 128)
        Ts[1 + (i >> 6)][i & 63] = lyb[i];
    __syncthreads();

    for (int p = tid; p < NPAIR; p += 128) {
        int i = (int)((1.0f + sqrtf(1.0f + 8.0f * (float)p)) * 0.5f);
        while (i * (i - 1) / 2 > p) i--;
        while ((i + 1) * i / 2 <= p) i++;
        int j = p - i * (i - 1) / 2;

        const float4* ri = (const float4*)&Ts[i][0];
        const float4* rj = (const float4*)&Ts[j][0];
        float acc = 0.f;
#pragma unroll
        for (int k = 0; k < EDIM / 4; k++) {
            float4 a = ri[k], c = rj[k];
            acc += a.x * c.x + a.y * c.y + a.z * c.z + a.w * c.w;
        }
        R[(ll)b * RDIM + 64 + p] = __float2bfloat16_rn(acc);
    }
    if (tid == 0) R[(ll)b * RDIM + 415] = __float2bfloat16_rn(0.f);
}

// ---------------- final layer ----------------
__global__ void __launch_bounds__(256)
gemv_sigmoid(const bf16* __restrict__ A, const float* __restrict__ w,
             const float* __restrict__ bias, float* __restrict__ out)
{
    const int row  = blockIdx.x * 8 + (threadIdx.x >> 5);
    const int lane = threadIdx.x & 31;
    float4 raw = *(const float4*)(A + (ll)row * 256 + lane * 8);
    const __nv_bfloat162* pr = (const __nv_bfloat162*)&raw;
    float s = 0.f;
#pragma unroll
    for (int i = 0; i < 4; i++) {
        float2 v = __bfloat1622float2(pr[i]);
        s += v.x * w[lane * 8 + 2 * i] + v.y * w[lane * 8 + 2 * i + 1];
    }
#pragma unroll
    for (int off = 16; off; off >>= 1) s += __shfl_xor_sync(0xffffffffu, s, off);
    if (lane == 0) out[row] = 1.f / (1.f + expf(-(s + bias[0])));
}

// ---------------- launch ----------------
extern "C" void kernel_launch(void* const* d_in, const int* in_sizes, int n_in,
                              void* d_out, int out_size)
{
    const float* x    = (const float*)d_in[0];
    const void*  lsi  = d_in[1];
    const float* emb  = (const float*)d_in[2];
    const float* bw0  = (const float*)d_in[3];
    const float* bb0  = (const float*)d_in[4];
    const float* bw1  = (const float*)d_in[5];
    const float* bb1  = (const float*)d_in[6];
    const float* bw2  = (const float*)d_in[7];
    const float* bb2  = (const float*)d_in[8];
    const float* tw0  = (const float*)d_in[9];
    const float* tb0  = (const float*)d_in[10];
    const float* tw1  = (const float*)d_in[11];
    const float* tb1  = (const float*)d_in[12];
    const float* tw2  = (const float*)d_in[13];
    const float* tb2  = (const float*)d_in[14];
    float* out = (float*)d_out;

    bf16 *bw1p, *bw2p, *tw0p, *tw1p, *h0, *h1, *R, *z0, *z1;
    float* ly;
    cudaGetSymbolAddress((void**)&bw1p, g_bw1p);
    cudaGetSymbolAddress((void**)&bw2p, g_bw2p);
    cudaGetSymbolAddress((void**)&tw0p, g_tw0p);
    cudaGetSymbolAddress((void**)&tw1p, g_tw1p);
    cudaGetSymbolAddress((void**)&h0,   g_h0);
    cudaGetSymbolAddress((void**)&h1,   g_h1);
    cudaGetSymbolAddress((void**)&R,    g_R);
    cudaGetSymbolAddress((void**)&z0,   g_z0);
    cudaGetSymbolAddress((void**)&z1,   g_z1);
    cudaGetSymbolAddress((void**)&ly,   g_ly);

    pack_all<<<1920, 256>>>(bw1, bw2, tw0, tw1);
    gather_kernel<<<(BATCH * NTAB * 16 + 255) / 256, 256>>>(lsi, emb, ly);

    // bottom MLP: L1 FFMA (fp32 in), L2 wmma, L3 FFMA -> R[:,0:64]
    mlp_l1<<<128, 256>>>(x, bw0, bb0, h0);
    gemm_bf16<1><<<dim3(4, 64), 128>>>(h0, bw1p, bb1, h1, 512, 256);
    mlp_l3<<<256, 256>>>(h1, bw2p, bb2, R);

    interact_kernel<<<BATCH, 128>>>(R, ly, R);

    // top MLP
    gemm_bf16<1><<<dim3(8, 64), 128>>>(R,  tw0p, tb0, z0, RDIM, 512);
    gemm_bf16<1><<<dim3(4, 64), 128>>>(z0, tw1p, tb1, z1, 512,  256);
    gemv_sigmoid<<<BATCH / 8, 256>>>(z1, tw2, tb2, out);
}

// round 11
// speedup vs baseline: 1.3138x; 1.3138x over previous
#include <cuda_runtime.h>
#include <cuda_bf16.h>
#include <mma.h>
#include <math.h>

using namespace nvcuda;

#define BATCH 4096
#define NTAB  26
#define VOC   100000
#define EDIM  64
#define NPAIR 351
#define RDIM  448          // 64 + 351 padded to mult of 64 (cols 415..447 zeroed)

typedef __nv_bfloat16 bf16;
typedef long long ll;

// ---------------- scratch ----------------
__device__ bf16  g_xp  [BATCH * 64];
__device__ bf16  g_bw0p[512 * 64];
__device__ bf16  g_bw1p[256 * 512];
__device__ bf16  g_bw2p[64 * 256];
__device__ bf16  g_tw0p[512 * RDIM];
__device__ bf16  g_tw1p[256 * 512];
__device__ bf16  g_h0  [BATCH * 512];
__device__ bf16  g_h1  [BATCH * 256];
__device__ bf16  g_R   [BATCH * RDIM];
__device__ bf16  g_z0  [BATCH * 512];
__device__ bf16  g_z1  [BATCH * 256];

// ---------------- helpers ----------------
__device__ __forceinline__ unsigned su(const void* p) {
    return (unsigned)__cvta_generic_to_shared(p);
}
__device__ __forceinline__ void cpa16(unsigned d, const void* s) {
    asm volatile("cp.async.cg.shared.global [%0], [%1], 16;\n" :: "r"(d), "l"(s));
}

// ---------------- pack: fp32 -> bf16, K padded to mult of 64 ----------------
__global__ void __launch_bounds__(256)
pack_all(const float* x, const float* bw0, const float* bw1, const float* bw2,
         const float* tw0, const float* tw1)
{
    ll gid = (ll)blockIdx.x * 256 + threadIdx.x;
    const float* src; bf16* dst; int K, Kp; ll e;
    if (gid < 262144)       { src = x;   dst = g_xp;   K = 13;  Kp = 64;   e = gid; }
    else if (gid < 294912)  { src = bw0; dst = g_bw0p; K = 13;  Kp = 64;   e = gid - 262144; }
    else if (gid < 425984)  { src = bw1; dst = g_bw1p; K = 512; Kp = 512;  e = gid - 294912; }
    else if (gid < 442368)  { src = bw2; dst = g_bw2p; K = 256; Kp = 256;  e = gid - 425984; }
    else if (gid < 671744)  { src = tw0; dst = g_tw0p; K = 415; Kp = RDIM; e = gid - 442368; }
    else if (gid < 802816)  { src = tw1; dst = g_tw1p; K = 512; Kp = 512;  e = gid - 671744; }
    else return;
    int n = (int)(e / Kp), k = (int)(e % Kp);
    float v = (k < K) ? src[(ll)n * K + k] : 0.f;
    dst[e] = __float2bfloat16_rn(v);
}

// ---------------- pipelined bf16 GEMM: BM=BN=64, BK=64, 128 thr (R4 + wider K) ----
template <int ACT>
__global__ void __launch_bounds__(128, 5)
gemm_bf16(const bf16* __restrict__ A, const bf16* __restrict__ W,
          const float* __restrict__ bias, bf16* __restrict__ C, int Kp, int ldc)
{
    constexpr int BM = 64, BN = 64, BK = 64, LDT = 72, LDCs = 36;
    __shared__ __align__(16) bf16 sm[2][(BM + BN) * LDT];   // 36.9 KB

    const int bm   = blockIdx.y * BM;
    const int bn   = blockIdx.x * BN;
    const int tid  = threadIdx.x;
    const int wid  = tid >> 5;
    const int lane = tid & 31;
    const int warp_m = wid & 1;
    const int warp_n = wid >> 1;
    const int nk = Kp / BK;

    wmma::fragment<wmma::accumulator, 16, 16, 16, float> acc[2][2];
#pragma unroll
    for (int i = 0; i < 2; i++)
#pragma unroll
        for (int j = 0; j < 2; j++) wmma::fill_fragment(acc[i][j], 0.f);

    // stage loader: A 64x64 (512 chunks of 16B) + W 64x64; 8 cp.async per thread
    auto load_stage = [&](int st, int k0) {
        bf16* As = sm[st];
        bf16* Ws = As + BM * LDT;
#pragma unroll
        for (int i = 0; i < 4; i++) {
            int id = tid + i * 128;
            int r = id >> 3, c8 = (id & 7) * 8;
            cpa16(su(As + r * LDT + c8), A + (ll)(bm + r) * Kp + k0 + c8);
        }
#pragma unroll
        for (int i = 0; i < 4; i++) {
            int id = tid + i * 128;
            int r = id >> 3, c8 = (id & 7) * 8;
            cpa16(su(Ws + r * LDT + c8), W + (ll)(bn + r) * Kp + k0 + c8);
        }
        asm volatile("cp.async.commit_group;\n");
    };

    load_stage(0, 0);

    for (int it = 0; it < nk; it++) {
        if (it + 1 < nk) {
            load_stage((it + 1) & 1, (it + 1) * BK);
            asm volatile("cp.async.wait_group 1;\n");
        } else {
            asm volatile("cp.async.wait_group 0;\n");
        }
        __syncthreads();

        const bf16* As = sm[it & 1];
        const bf16* Ws = As + BM * LDT;
#pragma unroll
        for (int kk = 0; kk < BK; kk += 16) {
            wmma::fragment<wmma::matrix_a, 16, 16, 16, bf16, wmma::row_major> af[2];
            wmma::fragment<wmma::matrix_b, 16, 16, 16, bf16, wmma::col_major> bfg[2];
#pragma unroll
            for (int i = 0; i < 2; i++)
                wmma::load_matrix_sync(af[i], As + (warp_m * 32 + i * 16) * LDT + kk, LDT);
#pragma unroll
            for (int j = 0; j < 2; j++)
                wmma::load_matrix_sync(bfg[j], Ws + (warp_n * 32 + j * 16) * LDT + kk, LDT);
#pragma unroll
            for (int i = 0; i < 2; i++)
#pragma unroll
                for (int j = 0; j < 2; j++)
                    wmma::mma_sync(acc[i][j], af[i], bfg[j], acc[i][j]);
        }
        __syncthreads();
    }

    // epilogue: park in smem (alias), bias+relu, coalesced store
    float* Cw = (float*)sm + wid * 32 * LDCs;
#pragma unroll
    for (int i = 0; i < 2; i++)
#pragma unroll
        for (int j = 0; j < 2; j++)
            wmma::store_matrix_sync(Cw + (i * 16) * LDCs + j * 16, acc[i][j], LDCs,
                                    wmma::mem_row_major);
    __syncwarp();

    const int n = bn + warp_n * 32 + lane;
    const float bv = bias[n];
#pragma unroll
    for (int r = 0; r < 32; r++) {
        int m = bm + warp_m * 32 + r;
        float v = Cw[r * LDCs + lane] + bv;
        if (ACT == 1) v = fmaxf(v, 0.f);
        C[(ll)m * ldc + n] = __float2bfloat16_rn(v);
    }
}

// ---------------- fused embedding gather + interaction ----------------
// One 128-thr block per batch row. Gather unit = (table, 16B quarter), summed
// over L=4 directly into shared T; then 351 tril dots -> R[:,64:415].
__global__ void __launch_bounds__(128)
gather_interact(const void* __restrict__ lsi, const float* __restrict__ emb,
                bf16* __restrict__ R)
{
    __shared__ float Ts[27][68];
    __shared__ int sidx[26][4];
    const int b   = blockIdx.x;
    const int tid = threadIdx.x;

    const unsigned long long* q = (const unsigned long long*)lsi;
    const bool is64 = (q[0] < (unsigned long long)VOC) && (q[1] < (unsigned long long)VOC) &&
                      (q[2] < (unsigned long long)VOC) && (q[3] < (unsigned long long)VOC);

    // h row (written by bottom-MLP L3 into R[:,0:64])
    if (tid < 64) Ts[0][tid] = __bfloat162float(R[(ll)b * RDIM + tid]);
    // indices for this row: 26 tables x 4
    if (tid < NTAB * 4) {
        int t = tid >> 2, l = tid & 3;
        ll pos = ((ll)t * BATCH + b) * 4 + l;
        sidx[t][l] = is64 ? (int)((const ll*)lsi)[pos] : ((const int*)lsi)[pos];
    }
    __syncthreads();

    // gather-sum: 26*16 = 416 units
    for (int u = tid; u < NTAB * 16; u += 128) {
        int t = u >> 4, q4 = u & 15;
        float4 s = make_float4(0.f, 0.f, 0.f, 0.f);
#pragma unroll
        for (int l = 0; l < 4; l++) {
            const float4 v = __ldg((const float4*)(emb +
                ((ll)t * VOC + sidx[t][l]) * EDIM + q4 * 4));
            s.x += v.x; s.y += v.y; s.z += v.z; s.w += v.w;
        }
        *(float4*)&Ts[1 + t][q4 * 4] = s;
    }
    __syncthreads();

    for (int p = tid; p < NPAIR; p += 128) {
        int i = (int)((1.0f + sqrtf(1.0f + 8.0f * (float)p)) * 0.5f);
        while (i * (i - 1) / 2 > p) i--;
        while ((i + 1) * i / 2 <= p) i++;
        int j = p - i * (i - 1) / 2;

        const float4* ri = (const float4*)&Ts[i][0];
        const float4* rj = (const float4*)&Ts[j][0];
        float acc = 0.f;
#pragma unroll
        for (int k = 0; k < EDIM / 4; k++) {
            float4 a = ri[k], c = rj[k];
            acc += a.x * c.x + a.y * c.y + a.z * c.z + a.w * c.w;
        }
        R[(ll)b * RDIM + 64 + p] = __float2bfloat16_rn(acc);
    }
    // zero padding cols 415..447 (tw0p is zero there too; keep deterministic)
    if (tid < RDIM - 64 - NPAIR)
        R[(ll)b * RDIM + 64 + NPAIR + tid] = __float2bfloat16_rn(0.f);
}

// ---------------- final layer ----------------
__global__ void __launch_bounds__(256)
gemv_sigmoid(const bf16* __restrict__ A, const float* __restrict__ w,
             const float* __restrict__ bias, float* __restrict__ out)
{
    const int row  = blockIdx.x * 8 + (threadIdx.x >> 5);
    const int lane = threadIdx.x & 31;
    float4 raw = *(const float4*)(A + (ll)row * 256 + lane * 8);
    const __nv_bfloat162* pr = (const __nv_bfloat162*)&raw;
    float s = 0.f;
#pragma unroll
    for (int i = 0; i < 4; i++) {
        float2 v = __bfloat1622float2(pr[i]);
        s += v.x * w[lane * 8 + 2 * i] + v.y * w[lane * 8 + 2 * i + 1];
    }
#pragma unroll
    for (int off = 16; off; off >>= 1) s += __shfl_xor_sync(0xffffffffu, s, off);
    if (lane == 0) out[row] = 1.f / (1.f + expf(-(s + bias[0])));
}

// ---------------- launch ----------------
extern "C" void kernel_launch(void* const* d_in, const int* in_sizes, int n_in,
                              void* d_out, int out_size)
{
    const float* x    = (const float*)d_in[0];
    const void*  lsi  = d_in[1];
    const float* emb  = (const float*)d_in[2];
    const float* bw0  = (const float*)d_in[3];
    const float* bb0  = (const float*)d_in[4];
    const float* bw1  = (const float*)d_in[5];
    const float* bb1  = (const float*)d_in[6];
    const float* bw2  = (const float*)d_in[7];
    const float* bb2  = (const float*)d_in[8];
    const float* tw0  = (const float*)d_in[9];
    const float* tb0  = (const float*)d_in[10];
    const float* tw1  = (const float*)d_in[11];
    const float* tb1  = (const float*)d_in[12];
    const float* tw2  = (const float*)d_in[13];
    const float* tb2  = (const float*)d_in[14];
    float* out = (float*)d_out;

    bf16 *xp, *bw0p, *bw1p, *bw2p, *tw0p, *tw1p, *h0, *h1, *R, *z0, *z1;
    cudaGetSymbolAddress((void**)&xp,   g_xp);
    cudaGetSymbolAddress((void**)&bw0p, g_bw0p);
    cudaGetSymbolAddress((void**)&bw1p, g_bw1p);
    cudaGetSymbolAddress((void**)&bw2p, g_bw2p);
    cudaGetSymbolAddress((void**)&tw0p, g_tw0p);
    cudaGetSymbolAddress((void**)&tw1p, g_tw1p);
    cudaGetSymbolAddress((void**)&h0,   g_h0);
    cudaGetSymbolAddress((void**)&h1,   g_h1);
    cudaGetSymbolAddress((void**)&R,    g_R);
    cudaGetSymbolAddress((void**)&z0,   g_z0);
    cudaGetSymbolAddress((void**)&z1,   g_z1);

    pack_all<<<3136, 256>>>(x, bw0, bw1, bw2, tw0, tw1);

    // bottom MLP; layer 3 writes into R[:, 0:64]
    gemm_bf16<1><<<dim3(8, 64), 128>>>(xp, bw0p, bb0, h0, 64,  512);
    gemm_bf16<1><<<dim3(4, 64), 128>>>(h0, bw1p, bb1, h1, 512, 256);
    gemm_bf16<1><<<dim3(1, 64), 128>>>(h1, bw2p, bb2, R,  256, RDIM);

    // fused gather + interaction -> R[:, 64:415] (+ zero pad)
    gather_interact<<<BATCH, 128>>>(lsi, emb, R);

    // top MLP
    gemm_bf16<1><<<dim3(8, 64), 128>>>(R,  tw0p, tb0, z0, RDIM, 512);
    gemm_bf16<1><<<dim3(4, 64), 128>>>(z0, tw1p, tb1, z1, 512,  256);
    gemv_sigmoid<<<BATCH / 8, 256>>>(z1, tw2, tb2, out);
}